// round 2
// baseline (speedup 1.0000x reference)
#include <cuda_runtime.h>
#include <cstdint>
#include <math.h>

// ============================================================================
// Shapes
// ============================================================================
#define M_TOTAL 8192
#define N_EMBD  1024
#define N_STATE 4096

// CTA tiling
#define CTA_M 128
#define CTA_N 128
#define CTA_K 32
#define STAGES 3

// Padded SMEM pitches (floats) — chosen for conflict-free fragment LDS:
//  A[m][k]: bank = (36m + k) % 32 = (4m + k) % 32 ; lanes vary g=m(0..7), t4=k(0..3) -> 4g+t4 unique
//  B[k][n]: bank = (136k + n) % 32 = (8k + n) % 32 ; lanes vary t4=k(0..3), g=n(0..7) -> 8t4+g unique
#define A_PITCH 36
#define B_PITCH 136
#define A_STAGE_FLOATS (CTA_M * A_PITCH)                 // 4608
#define B_STAGE_FLOATS (CTA_K * B_PITCH)                 // 4352
#define STAGE_FLOATS   (A_STAGE_FLOATS + B_STAGE_FLOATS) // 8960
#define SMEM_BYTES     (STAGES * STAGE_FLOATS * 4)       // 107520

// Hidden-layer scratch (static: no allocation allowed)
__device__ float g_H[(size_t)M_TOTAL * N_STATE];         // 128 MB

// ============================================================================
// PTX helpers (sm_100 base target: cp.async + mma.sync only, NO tcgen05)
// ============================================================================
__device__ __forceinline__ uint32_t smem_u32(const void* p) {
    uint32_t a;
    asm("{ .reg .u64 t; cvta.to.shared.u64 t, %1; cvt.u32.u64 %0, t; }" : "=r"(a) : "l"(p));
    return a;
}

__device__ __forceinline__ void cp_async16(uint32_t dst, const void* src) {
    asm volatile("cp.async.cg.shared.global [%0], [%1], 16;" :: "r"(dst), "l"(src));
}
__device__ __forceinline__ void cp_commit() {
    asm volatile("cp.async.commit_group;" ::: "memory");
}
template <int N>
__device__ __forceinline__ void cp_wait() {
    asm volatile("cp.async.wait_group %0;" :: "n"(N) : "memory");
}

// fp32 -> tf32 with round-to-nearest (RNA). Critical: HW truncation inside the
// MMA would add a correlated -2^-11 bias that blows the 1e-3 error budget.
__device__ __forceinline__ uint32_t f2tf32(float x) {
    uint32_t u;
    asm("cvt.rna.tf32.f32 %0, %1;" : "=r"(u) : "f"(x));
    return u;
}

__device__ __forceinline__ void mma_tf32(float* c, const uint32_t* a, const uint32_t* b) {
    asm volatile(
        "mma.sync.aligned.m16n8k8.row.col.f32.tf32.tf32.f32 "
        "{%0,%1,%2,%3}, {%4,%5,%6,%7}, {%8,%9}, {%0,%1,%2,%3};"
        : "+f"(c[0]), "+f"(c[1]), "+f"(c[2]), "+f"(c[3])
        : "r"(a[0]), "r"(a[1]), "r"(a[2]), "r"(a[3]), "r"(b[0]), "r"(b[1]));
}

__device__ __forceinline__ float gelu_exact(float x) {
    return 0.5f * x * (1.0f + erff(x * 0.70710678118654752f));
}

// ============================================================================
// GEMM: out[M, N] = op(A[M, K] @ B[K, N] + bias), op = GELU (exact) or identity
//   A row-major (K contiguous), B row-major (N contiguous) — NO transposes.
// ============================================================================
template <int DO_GELU>
__global__ void __launch_bounds__(256, 2)
mlp_gemm(const float* __restrict__ A, const float* __restrict__ B,
         const float* __restrict__ bias, float* __restrict__ out,
         int K, int N)
{
    extern __shared__ float smem[];

    const int tid  = threadIdx.x;
    const int wid  = tid >> 5;
    const int lane = tid & 31;
    const int g    = lane >> 2;     // group id (0..7)
    const int t4   = lane & 3;      // thread-in-group (0..3)
    const int wm   = wid & 3;       // warp M coord (4 warps * 32 rows = 128)
    const int wn   = wid >> 2;      // warp N coord (2 warps * 64 cols = 128)

    const int m0 = blockIdx.y * CTA_M;
    const int n0 = blockIdx.x * CTA_N;
    const int num_kt = K / CTA_K;

    // -------- stage loader (cp.async, 4 x 16B per thread per operand) --------
    auto load_stage = [&](int s, int kt) {
        float* aS = smem + s * STAGE_FLOATS;
        float* bS = aS + A_STAGE_FLOATS;
        const float* aG = A + (size_t)m0 * K + kt * CTA_K;
        const float* bG = B + (size_t)(kt * CTA_K) * N + n0;
        uint32_t aSb = smem_u32(aS);
        uint32_t bSb = smem_u32(bS);
        #pragma unroll
        for (int i = 0; i < 4; i++) {                 // A: 128 rows x 8 float4
            int c   = tid + i * 256;
            int row = c >> 3, col = c & 7;
            cp_async16(aSb + (row * A_PITCH + col * 4) * 4,
                       aG + (size_t)row * K + col * 4);
        }
        #pragma unroll
        for (int i = 0; i < 4; i++) {                 // B: 32 rows x 32 float4
            int c   = tid + i * 256;
            int row = c >> 5, col = c & 31;
            cp_async16(bSb + (row * B_PITCH + col * 4) * 4,
                       bG + (size_t)row * N + col * 4);
        }
    };

    float acc[2][8][4];
    #pragma unroll
    for (int mt = 0; mt < 2; mt++)
        #pragma unroll
        for (int ni = 0; ni < 8; ni++)
            #pragma unroll
            for (int j = 0; j < 4; j++) acc[mt][ni][j] = 0.0f;

    // -------- pipeline prologue: fill STAGES-1 stages --------
    load_stage(0, 0); cp_commit();
    load_stage(1, 1); cp_commit();

    // -------- mainloop --------
    for (int kt = 0; kt < num_kt; kt++) {
        cp_wait<STAGES - 2>();          // stage kt%3 data arrived
        __syncthreads();                // all warps done with stage being refilled

        if (kt + STAGES - 1 < num_kt) load_stage((kt + STAGES - 1) % STAGES, kt + STAGES - 1);
        cp_commit();                    // commit every iter (possibly empty group)

        const float* aS = smem + (kt % STAGES) * STAGE_FLOATS;
        const float* bS = aS + A_STAGE_FLOATS;
        const int am = wm * 32 + g;
        const int bn = wn * 64 + g;

        #pragma unroll
        for (int ks = 0; ks < 4; ks++) {            // 4 k-steps of 8
            const int kc = ks * 8 + t4;
            uint32_t af[2][4];
            #pragma unroll
            for (int mt = 0; mt < 2; mt++) {
                const float* ap = aS + (am + mt * 16) * A_PITCH + kc;
                af[mt][0] = f2tf32(ap[0]);
                af[mt][1] = f2tf32(ap[8 * A_PITCH]);
                af[mt][2] = f2tf32(ap[4]);
                af[mt][3] = f2tf32(ap[8 * A_PITCH + 4]);
            }
            uint32_t bf[8][2];
            #pragma unroll
            for (int ni = 0; ni < 8; ni++) {
                const float* bp = bS + kc * B_PITCH + bn + ni * 8;
                bf[ni][0] = f2tf32(bp[0]);
                bf[ni][1] = f2tf32(bp[4 * B_PITCH]);
            }
            #pragma unroll
            for (int mt = 0; mt < 2; mt++)
                #pragma unroll
                for (int ni = 0; ni < 8; ni++)
                    mma_tf32(acc[mt][ni], af[mt], bf[ni]);
        }
    }

    // -------- epilogue: bias (+GELU), fp32 store --------
    #pragma unroll
    for (int mt = 0; mt < 2; mt++) {
        const int row = m0 + wm * 32 + mt * 16 + g;
        #pragma unroll
        for (int ni = 0; ni < 8; ni++) {
            const int col = n0 + wn * 64 + ni * 8 + 2 * t4;
            const float2 bv = *reinterpret_cast<const float2*>(bias + col);
            float x0 = acc[mt][ni][0] + bv.x;
            float x1 = acc[mt][ni][1] + bv.y;
            float x2 = acc[mt][ni][2] + bv.x;
            float x3 = acc[mt][ni][3] + bv.y;
            if (DO_GELU) {
                x0 = gelu_exact(x0); x1 = gelu_exact(x1);
                x2 = gelu_exact(x2); x3 = gelu_exact(x3);
            }
            float2 v01 = {x0, x1}, v23 = {x2, x3};
            *reinterpret_cast<float2*>(out + (size_t)row * N + col)       = v01;
            *reinterpret_cast<float2*>(out + (size_t)(row + 8) * N + col) = v23;
        }
    }
}

// ============================================================================
// Host
// ============================================================================
extern "C" void kernel_launch(void* const* d_in, const int* in_sizes, int n_in,
                              void* d_out, int out_size) {
    const float* x  = (const float*)d_in[0];
    const float* w1 = (const float*)d_in[1];
    const float* b1 = (const float*)d_in[2];
    const float* w2 = (const float*)d_in[3];
    const float* b2 = (const float*)d_in[4];
    float* out = (float*)d_out;

    float* H;
    cudaGetSymbolAddress((void**)&H, g_H);

    cudaFuncSetAttribute(mlp_gemm<1>, cudaFuncAttributeMaxDynamicSharedMemorySize, SMEM_BYTES);
    cudaFuncSetAttribute(mlp_gemm<0>, cudaFuncAttributeMaxDynamicSharedMemorySize, SMEM_BYTES);

    // GEMM1: H = GELU(X @ W1 + b1)   X:[8192,1024]  W1:[1024,4096]
    mlp_gemm<1><<<dim3(N_STATE / CTA_N, M_TOTAL / CTA_M), 256, SMEM_BYTES>>>(
        x, w1, b1, H, N_EMBD, N_STATE);

    // GEMM2: out = H @ W2 + b2       H:[8192,4096]  W2:[4096,1024]
    mlp_gemm<0><<<dim3(N_EMBD / CTA_N, M_TOTAL / CTA_M), 256, SMEM_BYTES>>>(
        H, w2, b2, out, N_STATE, N_EMBD);
}

// round 3
// speedup vs baseline: 1.1543x; 1.1543x over previous
#include <cuda_runtime.h>
#include <cstdint>
#include <math.h>

// ============================================================================
// Shapes
// ============================================================================
#define M_TOTAL 8192
#define N_EMBD  1024
#define N_STATE 4096

// CTA tiling: 128 x 256 x 32, 8 warps of 64x64
#define CTA_M 128
#define CTA_N 256
#define CTA_K 32
#define STAGES 3

// Padded SMEM pitches (floats) — conflict-free fragment LDS:
//  A[m][k]: bank = (36m + k) % 32 = (4m + k) % 32 ; lanes: 4g + t4 unique
//  B[k][n]: bank = (264k + n) % 32 = (8k + n) % 32 ; lanes: 8t4 + g unique
#define A_PITCH 36
#define B_PITCH 264
#define A_STAGE_FLOATS (CTA_M * A_PITCH)                 // 4608
#define B_STAGE_FLOATS (CTA_K * B_PITCH)                 // 8448
#define STAGE_FLOATS   (A_STAGE_FLOATS + B_STAGE_FLOATS) // 13056
#define SMEM_BYTES     (STAGES * STAGE_FLOATS * 4)       // 156672

// Scratch (static: no allocation allowed). Operands pre-rounded to tf32 so the
// GEMM mainloop needs ZERO cvt instructions (HW truncation becomes exact).
__device__ float g_Xr [(size_t)M_TOTAL * N_EMBD];        //  32 MB
__device__ float g_W1r[(size_t)N_EMBD * N_STATE];        //  16 MB
__device__ float g_W2r[(size_t)N_STATE * N_EMBD];        //  16 MB
__device__ float g_H  [(size_t)M_TOTAL * N_STATE];       // 128 MB

// ============================================================================
// PTX helpers (sm_100 base target: cp.async + mma.sync, NO tcgen05)
// ============================================================================
__device__ __forceinline__ uint32_t smem_u32(const void* p) {
    uint32_t a;
    asm("{ .reg .u64 t; cvta.to.shared.u64 t, %1; cvt.u32.u64 %0, t; }" : "=r"(a) : "l"(p));
    return a;
}

__device__ __forceinline__ void cp_async16(uint32_t dst, const void* src) {
    asm volatile("cp.async.cg.shared.global [%0], [%1], 16;" :: "r"(dst), "l"(src));
}
__device__ __forceinline__ void cp_commit() {
    asm volatile("cp.async.commit_group;" ::: "memory");
}
template <int N>
__device__ __forceinline__ void cp_wait() {
    asm volatile("cp.async.wait_group %0;" :: "n"(N) : "memory");
}

__device__ __forceinline__ float to_tf32(float x) {
    uint32_t u;
    asm("cvt.rna.tf32.f32 %0, %1;" : "=r"(u) : "f"(x));
    return __uint_as_float(u);
}

__device__ __forceinline__ void mma_tf32(float* c, const uint32_t* a, const uint32_t* b) {
    asm volatile(
        "mma.sync.aligned.m16n8k8.row.col.f32.tf32.tf32.f32 "
        "{%0,%1,%2,%3}, {%4,%5,%6,%7}, {%8,%9}, {%0,%1,%2,%3};"
        : "+f"(c[0]), "+f"(c[1]), "+f"(c[2]), "+f"(c[3])
        : "r"(a[0]), "r"(a[1]), "r"(a[2]), "r"(a[3]), "r"(b[0]), "r"(b[1]));
}

__device__ __forceinline__ float gelu_exact(float x) {
    return 0.5f * x * (1.0f + erff(x * 0.70710678118654752f));
}

// ============================================================================
// Prepass: tf32 RNA-round in place into scratch (vectorized, grid-stride)
// ============================================================================
__global__ void round_tf32_kernel(const float* __restrict__ in, float* __restrict__ out, int n4) {
    int stride = gridDim.x * blockDim.x;
    for (int i = blockIdx.x * blockDim.x + threadIdx.x; i < n4; i += stride) {
        float4 v = reinterpret_cast<const float4*>(in)[i];
        v.x = to_tf32(v.x); v.y = to_tf32(v.y); v.z = to_tf32(v.z); v.w = to_tf32(v.w);
        reinterpret_cast<float4*>(out)[i] = v;
    }
}

// ============================================================================
// GEMM: out[M, N] = op(A[M, K] @ B[K, N] + bias)
//   A row-major (K contig), B row-major (N contig). Operands pre-rounded tf32.
//   DO_GELU: exact-erf GELU + tf32-round the output (feeds next GEMM).
// ============================================================================
template <int DO_GELU>
__global__ void __launch_bounds__(256, 1)
mlp_gemm(const float* __restrict__ A, const float* __restrict__ B,
         const float* __restrict__ bias, float* __restrict__ out,
         int K, int N)
{
    extern __shared__ float smem[];

    const int tid  = threadIdx.x;
    const int wid  = tid >> 5;
    const int lane = tid & 31;
    const int g    = lane >> 2;     // 0..7
    const int t4   = lane & 3;      // 0..3
    const int wm   = wid & 1;       // 2 warps in M (64 rows each)
    const int wn   = wid >> 1;      // 4 warps in N (64 cols each)

    const int m0 = blockIdx.y * CTA_M;
    const int n0 = blockIdx.x * CTA_N;
    const int num_kt = K / CTA_K;

    // -------- stage loader: A 4 x f4, B 8 x f4 per thread --------
    auto load_stage = [&](int s, int kt) {
        float* aS = smem + s * STAGE_FLOATS;
        float* bS = aS + A_STAGE_FLOATS;
        const float* aG = A + (size_t)m0 * K + kt * CTA_K;
        const float* bG = B + (size_t)(kt * CTA_K) * N + n0;
        uint32_t aSb = smem_u32(aS);
        uint32_t bSb = smem_u32(bS);
        #pragma unroll
        for (int i = 0; i < 4; i++) {                 // A: 128 rows x 8 float4
            int c = tid + i * 256;
            int row = c >> 3, col = c & 7;
            cp_async16(aSb + (row * A_PITCH + col * 4) * 4,
                       aG + (size_t)row * K + col * 4);
        }
        #pragma unroll
        for (int i = 0; i < 8; i++) {                 // B: 32 rows x 64 float4
            int c = tid + i * 256;
            int row = c >> 6, col = c & 63;
            cp_async16(bSb + (row * B_PITCH + col * 4) * 4,
                       bG + (size_t)row * N + col * 4);
        }
    };

    float acc[4][8][4];
    #pragma unroll
    for (int mt = 0; mt < 4; mt++)
        #pragma unroll
        for (int ni = 0; ni < 8; ni++)
            #pragma unroll
            for (int j = 0; j < 4; j++) acc[mt][ni][j] = 0.0f;

    load_stage(0, 0); cp_commit();
    load_stage(1, 1); cp_commit();

    const int am = wm * 64 + g;
    const int bn = wn * 64 + g;

    for (int kt = 0; kt < num_kt; kt++) {
        cp_wait<STAGES - 2>();
        __syncthreads();

        if (kt + STAGES - 1 < num_kt) load_stage((kt + STAGES - 1) % STAGES, kt + STAGES - 1);
        cp_commit();

        const uint32_t* aS = reinterpret_cast<const uint32_t*>(smem + (kt % STAGES) * STAGE_FLOATS);
        const uint32_t* bS = aS + A_STAGE_FLOATS;

        #pragma unroll
        for (int ks = 0; ks < 4; ks++) {              // 4 k-steps of 8
            const int kc = ks * 8 + t4;
            uint32_t af[4][4];
            #pragma unroll
            for (int mt = 0; mt < 4; mt++) {
                const uint32_t* ap = aS + (am + mt * 16) * A_PITCH + kc;
                af[mt][0] = ap[0];
                af[mt][1] = ap[8 * A_PITCH];
                af[mt][2] = ap[4];
                af[mt][3] = ap[8 * A_PITCH + 4];
            }
            uint32_t bf[8][2];
            #pragma unroll
            for (int ni = 0; ni < 8; ni++) {
                const uint32_t* bp = bS + kc * B_PITCH + bn + ni * 8;
                bf[ni][0] = bp[0];
                bf[ni][1] = bp[4 * B_PITCH];
            }
            #pragma unroll
            for (int mt = 0; mt < 4; mt++)
                #pragma unroll
                for (int ni = 0; ni < 8; ni++)
                    mma_tf32(acc[mt][ni], af[mt], bf[ni]);
        }
    }

    // -------- epilogue: bias (+GELU, +tf32 round), fp32 stores --------
    #pragma unroll
    for (int mt = 0; mt < 4; mt++) {
        const int row = m0 + wm * 64 + mt * 16 + g;
        #pragma unroll
        for (int ni = 0; ni < 8; ni++) {
            const int col = n0 + wn * 64 + ni * 8 + 2 * t4;
            const float2 bv = *reinterpret_cast<const float2*>(bias + col);
            float x0 = acc[mt][ni][0] + bv.x;
            float x1 = acc[mt][ni][1] + bv.y;
            float x2 = acc[mt][ni][2] + bv.x;
            float x3 = acc[mt][ni][3] + bv.y;
            if (DO_GELU) {
                // round so GEMM2's HW tf32 truncation of H is exact
                x0 = to_tf32(gelu_exact(x0)); x1 = to_tf32(gelu_exact(x1));
                x2 = to_tf32(gelu_exact(x2)); x3 = to_tf32(gelu_exact(x3));
            }
            float2 v01 = {x0, x1}, v23 = {x2, x3};
            *reinterpret_cast<float2*>(out + (size_t)row * N + col)       = v01;
            *reinterpret_cast<float2*>(out + (size_t)(row + 8) * N + col) = v23;
        }
    }
}

// ============================================================================
// Host
// ============================================================================
extern "C" void kernel_launch(void* const* d_in, const int* in_sizes, int n_in,
                              void* d_out, int out_size) {
    const float* x  = (const float*)d_in[0];
    const float* w1 = (const float*)d_in[1];
    const float* b1 = (const float*)d_in[2];
    const float* w2 = (const float*)d_in[3];
    const float* b2 = (const float*)d_in[4];
    float* out = (float*)d_out;

    float *Xr, *W1r, *W2r, *H;
    cudaGetSymbolAddress((void**)&Xr,  g_Xr);
    cudaGetSymbolAddress((void**)&W1r, g_W1r);
    cudaGetSymbolAddress((void**)&W2r, g_W2r);
    cudaGetSymbolAddress((void**)&H,   g_H);

    cudaFuncSetAttribute(mlp_gemm<1>, cudaFuncAttributeMaxDynamicSharedMemorySize, SMEM_BYTES);
    cudaFuncSetAttribute(mlp_gemm<0>, cudaFuncAttributeMaxDynamicSharedMemorySize, SMEM_BYTES);

    // Prepass: RNA-round operands to tf32 (removes all mainloop CVTs)
    round_tf32_kernel<<<1184, 256>>>(x,  Xr,  (M_TOTAL * N_EMBD) / 4);
    round_tf32_kernel<<<1184, 256>>>(w1, W1r, (N_EMBD * N_STATE) / 4);
    round_tf32_kernel<<<1184, 256>>>(w2, W2r, (N_STATE * N_EMBD) / 4);

    // GEMM1: H = tf32(GELU(X @ W1 + b1))
    mlp_gemm<1><<<dim3(N_STATE / CTA_N, M_TOTAL / CTA_M), 256, SMEM_BYTES>>>(
        Xr, W1r, b1, H, N_EMBD, N_STATE);

    // GEMM2: out = H @ W2 + b2
    mlp_gemm<0><<<dim3(N_EMBD / CTA_N, M_TOTAL / CTA_M), 256, SMEM_BYTES>>>(
        H, W2r, b2, out, N_STATE, N_EMBD);
}

// round 4
// speedup vs baseline: 1.7455x; 1.5122x over previous
#include <cuda_runtime.h>
#include <cuda_fp16.h>
#include <cstdint>
#include <math.h>

// ============================================================================
// Shapes
// ============================================================================
#define M_TOTAL 8192
#define N_EMBD  1024
#define N_STATE 4096

#define CTA_M  128
#define CTA_K  32          // K per tile (fp16: 2 k-steps of 16)
#define STAGES 4

// SMEM pitch: 40 halves (80 B) per row -> fragment LDS.32 bank = (20g+t4)%32,
// a full 32-lane permutation (verified): conflict-free.
#define PITCH_H   40
#define PITCH_U32 20
#define A_STAGE_BYTES (CTA_M * PITCH_H * 2)              // 10240
#define B_STAGE_BYTES(CTAN) ((CTAN) * PITCH_H * 2)
#define STAGE_BYTES(CTAN)   (A_STAGE_BYTES + B_STAGE_BYTES(CTAN))
#define SMEM_BYTES(CTAN)    (STAGES * STAGE_BYTES(CTAN))

// Scratch (static; no allocation allowed)
__device__ __half g_Xh [(size_t)M_TOTAL * N_EMBD];       // 16 MB
__device__ __half g_W1t[(size_t)N_STATE * N_EMBD];       //  8 MB  [N_STATE][N_EMBD]
__device__ __half g_W2t[(size_t)N_EMBD * N_STATE];       //  8 MB  [N_EMBD][N_STATE]
__device__ __half g_H  [(size_t)M_TOTAL * N_STATE];      // 64 MB

// ============================================================================
// PTX helpers (sm_100 base: cp.async + mma.sync fp16)
// ============================================================================
__device__ __forceinline__ uint32_t smem_u32(const void* p) {
    uint32_t a;
    asm("{ .reg .u64 t; cvta.to.shared.u64 t, %1; cvt.u32.u64 %0, t; }" : "=r"(a) : "l"(p));
    return a;
}
__device__ __forceinline__ void cp_async16(uint32_t dst, const void* src) {
    asm volatile("cp.async.cg.shared.global [%0], [%1], 16;" :: "r"(dst), "l"(src));
}
__device__ __forceinline__ void cp_commit() {
    asm volatile("cp.async.commit_group;" ::: "memory");
}
template <int N>
__device__ __forceinline__ void cp_wait() {
    asm volatile("cp.async.wait_group %0;" :: "n"(N) : "memory");
}

__device__ __forceinline__ void mma_f16(float* c, const uint32_t* a, const uint32_t* b) {
    asm volatile(
        "mma.sync.aligned.m16n8k16.row.col.f32.f16.f16.f32 "
        "{%0,%1,%2,%3}, {%4,%5,%6,%7}, {%8,%9}, {%0,%1,%2,%3};"
        : "+f"(c[0]), "+f"(c[1]), "+f"(c[2]), "+f"(c[3])
        : "r"(a[0]), "r"(a[1]), "r"(a[2]), "r"(a[3]), "r"(b[0]), "r"(b[1]));
}

__device__ __forceinline__ float gelu_exact(float x) {
    return 0.5f * x * (1.0f + erff(x * 0.70710678118654752f));
}

// ============================================================================
// Prepass: fp32 -> fp16 (RNE), straight copy and 32x32 transpose
// ============================================================================
__global__ void f32_to_f16_kernel(const float* __restrict__ in, __half* __restrict__ out, int n4) {
    int stride = gridDim.x * blockDim.x;
    for (int i = blockIdx.x * blockDim.x + threadIdx.x; i < n4; i += stride) {
        float4 v = reinterpret_cast<const float4*>(in)[i];
        __half2* o = reinterpret_cast<__half2*>(out) + 2 * i;
        o[0] = __floats2half2_rn(v.x, v.y);
        o[1] = __floats2half2_rn(v.z, v.w);
    }
}

// in fp32 [rows][cols] -> out fp16 [cols][rows]. block (32,8), grid (cols/32, rows/32)
__global__ void transpose_f16_kernel(const float* __restrict__ in, __half* __restrict__ out,
                                     int rows, int cols) {
    __shared__ float tile[32][33];
    int bx = blockIdx.x * 32, by = blockIdx.y * 32;
    int tx = threadIdx.x;
    for (int r = threadIdx.y; r < 32; r += 8)
        tile[r][tx] = in[(size_t)(by + r) * cols + bx + tx];
    __syncthreads();
    for (int r = threadIdx.y; r < 32; r += 8)
        out[(size_t)(bx + r) * rows + by + tx] = __float2half_rn(tile[tx][r]);
}

// ============================================================================
// GEMM: out[M,N] = op(A[M,K] @ Bt[N,K]^T + bias)
//   A fp16 [M][K] row-major; Bt fp16 [N][K] row-major (pre-transposed weights).
//   DO_GELU=1: exact GELU, fp16 output (feeds GEMM2). DO_GELU=0: fp32 output.
//   8 warps: 2 in M (64 rows) x 4 in N (CTAN/4 cols each).
// ============================================================================
template <int DO_GELU, int CTAN, int MINB>
__global__ void __launch_bounds__(256, MINB)
mlp_gemm_h(const __half* __restrict__ A, const __half* __restrict__ Bt,
           const float* __restrict__ bias, void* __restrict__ outp,
           int K, int N)
{
    constexpr int NI    = CTAN / 32;    // B fragments (8-wide) per warp
    constexpr int WSPAN = CTAN / 4;     // warp N span
    extern __shared__ __half smem[];

    const int tid  = threadIdx.x;
    const int wid  = tid >> 5;
    const int lane = tid & 31;
    const int g    = lane >> 2;         // 0..7
    const int t4   = lane & 3;          // 0..3
    const int wm   = wid & 1;           // 2 warps in M
    const int wn   = wid >> 1;          // 4 warps in N

    const int m0 = blockIdx.y * CTA_M;
    const int n0 = blockIdx.x * CTAN;
    const int num_kt = K / CTA_K;

    constexpr int STAGE_H   = CTA_M * PITCH_H + CTAN * PITCH_H;
    constexpr int A_STAGE_H = CTA_M * PITCH_H;

    // -------- stage loader: 16B chunks (8 halves), 4 chunks per row --------
    auto load_stage = [&](int s, int kt) {
        __half* aS = smem + s * STAGE_H;
        __half* bS = aS + A_STAGE_H;
        const __half* aG = A  + (size_t)m0 * K + kt * CTA_K;
        const __half* bG = Bt + (size_t)n0 * K + kt * CTA_K;
        uint32_t aSb = smem_u32(aS);
        uint32_t bSb = smem_u32(bS);
        #pragma unroll
        for (int i = 0; i < (CTA_M * 4) / 256; i++) {      // A: 128 rows x 4 chunks
            int c = tid + i * 256;
            int row = c >> 2, ch = c & 3;
            cp_async16(aSb + row * (PITCH_H * 2) + ch * 16,
                       aG + (size_t)row * K + ch * 8);
        }
        #pragma unroll
        for (int i = 0; i < (CTAN * 4) / 256; i++) {       // B: CTAN rows x 4 chunks
            int c = tid + i * 256;
            int row = c >> 2, ch = c & 3;
            cp_async16(bSb + row * (PITCH_H * 2) + ch * 16,
                       bG + (size_t)row * K + ch * 8);
        }
    };

    float acc[4][NI][4];
    #pragma unroll
    for (int mt = 0; mt < 4; mt++)
        #pragma unroll
        for (int ni = 0; ni < NI; ni++)
            #pragma unroll
            for (int j = 0; j < 4; j++) acc[mt][ni][j] = 0.0f;

    load_stage(0, 0); cp_commit();
    load_stage(1, 1); cp_commit();
    load_stage(2, 2); cp_commit();

    const int am = wm * 64 + g;
    const int bn = wn * WSPAN + g;

    for (int kt = 0; kt < num_kt; kt++) {
        cp_wait<STAGES - 2>();
        __syncthreads();

        if (kt + STAGES - 1 < num_kt) load_stage((kt + STAGES - 1) % STAGES, kt + STAGES - 1);
        cp_commit();

        const uint32_t* aU = reinterpret_cast<const uint32_t*>(smem + (kt % STAGES) * STAGE_H);
        const uint32_t* bU = aU + A_STAGE_H / 2;

        #pragma unroll
        for (int ks = 0; ks < 2; ks++) {                   // 2 k-steps of 16
            const int kc = ks * 8 + t4;                    // u32 (half2) index
            uint32_t af[4][4];
            #pragma unroll
            for (int mt = 0; mt < 4; mt++) {
                const uint32_t* ap = aU + (am + mt * 16) * PITCH_U32 + kc;
                af[mt][0] = ap[0];
                af[mt][1] = ap[8 * PITCH_U32];
                af[mt][2] = ap[4];
                af[mt][3] = ap[8 * PITCH_U32 + 4];
            }
            uint32_t bf[NI][2];
            #pragma unroll
            for (int ni = 0; ni < NI; ni++) {
                const uint32_t* bp = bU + (bn + ni * 8) * PITCH_U32 + kc;
                bf[ni][0] = bp[0];
                bf[ni][1] = bp[4];
            }
            #pragma unroll
            for (int mt = 0; mt < 4; mt++)
                #pragma unroll
                for (int ni = 0; ni < NI; ni++)
                    mma_f16(acc[mt][ni], af[mt], bf[ni]);
        }
    }

    // -------- epilogue --------
    #pragma unroll
    for (int mt = 0; mt < 4; mt++) {
        const int row = m0 + wm * 64 + mt * 16 + g;
        #pragma unroll
        for (int ni = 0; ni < NI; ni++) {
            const int col = n0 + wn * WSPAN + ni * 8 + 2 * t4;
            const float2 bv = *reinterpret_cast<const float2*>(bias + col);
            float x0 = acc[mt][ni][0] + bv.x;
            float x1 = acc[mt][ni][1] + bv.y;
            float x2 = acc[mt][ni][2] + bv.x;
            float x3 = acc[mt][ni][3] + bv.y;
            if (DO_GELU) {
                __half* out = (__half*)outp;
                __half2 h01 = __floats2half2_rn(gelu_exact(x0), gelu_exact(x1));
                __half2 h23 = __floats2half2_rn(gelu_exact(x2), gelu_exact(x3));
                *reinterpret_cast<__half2*>(out + (size_t)row * N + col)       = h01;
                *reinterpret_cast<__half2*>(out + (size_t)(row + 8) * N + col) = h23;
            } else {
                float* out = (float*)outp;
                float2 v01 = {x0, x1}, v23 = {x2, x3};
                *reinterpret_cast<float2*>(out + (size_t)row * N + col)       = v01;
                *reinterpret_cast<float2*>(out + (size_t)(row + 8) * N + col) = v23;
            }
        }
    }
}

// ============================================================================
// Host
// ============================================================================
extern "C" void kernel_launch(void* const* d_in, const int* in_sizes, int n_in,
                              void* d_out, int out_size) {
    const float* x  = (const float*)d_in[0];
    const float* w1 = (const float*)d_in[1];
    const float* b1 = (const float*)d_in[2];
    const float* w2 = (const float*)d_in[3];
    const float* b2 = (const float*)d_in[4];
    float* out = (float*)d_out;

    __half *Xh, *W1t, *W2t, *H;
    cudaGetSymbolAddress((void**)&Xh,  g_Xh);
    cudaGetSymbolAddress((void**)&W1t, g_W1t);
    cudaGetSymbolAddress((void**)&W2t, g_W2t);
    cudaGetSymbolAddress((void**)&H,   g_H);

    cudaFuncSetAttribute((const void*)mlp_gemm_h<1, 256, 1>,
                         cudaFuncAttributeMaxDynamicSharedMemorySize, SMEM_BYTES(256));
    cudaFuncSetAttribute((const void*)mlp_gemm_h<0, 128, 2>,
                         cudaFuncAttributeMaxDynamicSharedMemorySize, SMEM_BYTES(128));

    // Prepass: X -> fp16; W1, W2 -> fp16 transposed to [N][K]
    f32_to_f16_kernel<<<1184, 256>>>(x, Xh, (M_TOTAL * N_EMBD) / 4);
    transpose_f16_kernel<<<dim3(N_STATE / 32, N_EMBD / 32), dim3(32, 8)>>>(w1, W1t, N_EMBD, N_STATE);
    transpose_f16_kernel<<<dim3(N_EMBD / 32, N_STATE / 32), dim3(32, 8)>>>(w2, W2t, N_STATE, N_EMBD);

    // GEMM1: H = fp16(GELU(X @ W1 + b1))   grid 16 x 64
    mlp_gemm_h<1, 256, 1><<<dim3(N_STATE / 256, M_TOTAL / CTA_M), 256, SMEM_BYTES(256)>>>(
        Xh, W1t, b1, H, N_EMBD, N_STATE);

    // GEMM2: out = H @ W2 + b2             grid 8 x 64, 2 CTAs/SM
    mlp_gemm_h<0, 128, 2><<<dim3(N_EMBD / 128, M_TOTAL / CTA_M), 256, SMEM_BYTES(128)>>>(
        H, W2t, b2, out, N_STATE, N_EMBD);
}

// round 5
// speedup vs baseline: 2.0957x; 1.2006x over previous
#include <cuda_runtime.h>
#include <cuda_fp16.h>
#include <cstdint>
#include <math.h>

// ============================================================================
// Shapes
// ============================================================================
#define M_TOTAL 8192
#define N_EMBD  1024
#define N_STATE 4096

// CTA 128x128x32, 8 warps of 64x32, 2 CTAs/SM
#define CTA_M  128
#define CTA_N  128
#define CTA_K  32                   // halves per k-tile (2 k-steps of 16)
#define STAGES 4

#define PITCH_B   80                // bytes per smem row (32 halves + 16B pad)
#define ROWS_PER_STAGE (CTA_M + CTA_N)              // 256
#define STAGE_BYTES    (ROWS_PER_STAGE * PITCH_B)   // 20480
#define SMEM_BYTES     (STAGES * STAGE_BYTES)       // 81920

// Scratch (static; no allocation allowed)
__device__ __half g_Xh [(size_t)M_TOTAL * N_EMBD];       // 16 MB
__device__ __half g_W1t[(size_t)N_STATE * N_EMBD];       //  8 MB  [N][K]
__device__ __half g_W2t[(size_t)N_EMBD * N_STATE];       //  8 MB  [N][K]
__device__ __half g_H  [(size_t)M_TOTAL * N_STATE];      // 64 MB

// ============================================================================
// PTX helpers
// ============================================================================
__device__ __forceinline__ uint32_t smem_u32(const void* p) {
    uint32_t a;
    asm("{ .reg .u64 t; cvta.to.shared.u64 t, %1; cvt.u32.u64 %0, t; }" : "=r"(a) : "l"(p));
    return a;
}
__device__ __forceinline__ void cp_async16(uint32_t dst, const void* src) {
    asm volatile("cp.async.cg.shared.global [%0], [%1], 16;" :: "r"(dst), "l"(src));
}
__device__ __forceinline__ void cp_commit() {
    asm volatile("cp.async.commit_group;" ::: "memory");
}
template <int N>
__device__ __forceinline__ void cp_wait() {
    asm volatile("cp.async.wait_group %0;" :: "n"(N) : "memory");
}
__device__ __forceinline__ void ldsm_x4(uint32_t* r, uint32_t addr) {
    asm volatile("ldmatrix.sync.aligned.m8n8.x4.shared.b16 {%0,%1,%2,%3}, [%4];"
        : "=r"(r[0]), "=r"(r[1]), "=r"(r[2]), "=r"(r[3]) : "r"(addr));
}
__device__ __forceinline__ void mma_f16(float* c, const uint32_t* a, const uint32_t* b) {
    asm volatile(
        "mma.sync.aligned.m16n8k16.row.col.f32.f16.f16.f32 "
        "{%0,%1,%2,%3}, {%4,%5,%6,%7}, {%8,%9}, {%0,%1,%2,%3};"
        : "+f"(c[0]), "+f"(c[1]), "+f"(c[2]), "+f"(c[3])
        : "r"(a[0]), "r"(a[1]), "r"(a[2]), "r"(a[3]), "r"(b[0]), "r"(b[1]));
}
__device__ __forceinline__ float gelu_exact(float x) {
    return 0.5f * x * (1.0f + erff(x * 0.70710678118654752f));
}

// ============================================================================
// Prepass: fp32 -> fp16 (RNE) copy + 32x32 transpose
// ============================================================================
__global__ void f32_to_f16_kernel(const float* __restrict__ in, __half* __restrict__ out, int n4) {
    int stride = gridDim.x * blockDim.x;
    for (int i = blockIdx.x * blockDim.x + threadIdx.x; i < n4; i += stride) {
        float4 v = reinterpret_cast<const float4*>(in)[i];
        __half2* o = reinterpret_cast<__half2*>(out) + 2 * i;
        o[0] = __floats2half2_rn(v.x, v.y);
        o[1] = __floats2half2_rn(v.z, v.w);
    }
}
__global__ void transpose_f16_kernel(const float* __restrict__ in, __half* __restrict__ out,
                                     int rows, int cols) {
    __shared__ float tile[32][33];
    int bx = blockIdx.x * 32, by = blockIdx.y * 32;
    int tx = threadIdx.x;
    for (int r = threadIdx.y; r < 32; r += 8)
        tile[r][tx] = in[(size_t)(by + r) * cols + bx + tx];
    __syncthreads();
    for (int r = threadIdx.y; r < 32; r += 8)
        out[(size_t)(bx + r) * rows + by + tx] = __float2half_rn(tile[tx][r]);
}

// ============================================================================
// GEMM: out[M,N] = op(A[M,K] @ Bt[N,K]^T + bias)
//   A fp16 [M][K]; Bt fp16 [N][K]. DO_GELU=1 -> fp16 out (H), else fp32 out.
//   SMEM stage: 256 rows x 80B (rows 0-127 = A, 128-255 = B), pitch-80 is a
//   full 32-bank permutation for LDSM 8-lane phases (20r mod 32 distinct).
// ============================================================================
template <int DO_GELU>
__global__ void __launch_bounds__(256, 2)
mlp_gemm_h(const __half* __restrict__ A, const __half* __restrict__ Bt,
           const float* __restrict__ bias, void* __restrict__ outp,
           int K, int N)
{
    extern __shared__ __half smem[];
    const uint32_t smem_base = smem_u32(smem);

    const int tid  = threadIdx.x;
    const int wid  = tid >> 5;
    const int lane = tid & 31;
    const int g    = lane >> 2;
    const int t4   = lane & 3;
    const int wm   = wid & 1;           // 2 warps in M (64 rows)
    const int wn   = wid >> 1;          // 4 warps in N (32 cols)

    const int m0 = blockIdx.y * CTA_M;
    const int n0 = blockIdx.x * CTA_N;
    const int num_kt = K / CTA_K;

    // ---- per-lane ldmatrix offsets (bytes) ----
    const int mi = lane >> 3;                     // matrix index 0..3
    const int r8 = lane & 7;                      // row within 8x8
    // A matrices: (m +0/+8) x (k +0/+16B):  m_off=(mi&1)*8, k_off=(mi>>1)*16
    const uint32_t a_lane = (uint32_t)(((mi & 1) * 8 + r8) * PITCH_B + (mi >> 1) * 16);
    // B matrices: (n +0/+8) x (k +0/+16B):  n_off=(mi>>1)*8, k_off=(mi&1)*16
    const uint32_t b_lane = (uint32_t)(((mi >> 1) * 8 + r8) * PITCH_B + (mi & 1) * 16);
    const uint32_t aw_base = smem_base + (uint32_t)(wm * 64) * PITCH_B + a_lane;
    const uint32_t bw_base = smem_base + (uint32_t)(CTA_M + wn * 32) * PITCH_B + b_lane;

    // ---- stage loader: 1024 chunks of 16B, 4 per thread ----
    auto load_stage = [&](int s, int kt) {
        uint32_t dstS = smem_base + (uint32_t)s * STAGE_BYTES;
        const __half* aG = A  + (size_t)m0 * K + kt * CTA_K;
        const __half* bG = Bt + (size_t)n0 * K + kt * CTA_K;
        #pragma unroll
        for (int i = 0; i < 4; i++) {
            int c   = tid + i * 256;
            int row = c >> 2, ch = c & 3;
            const __half* src = (row < CTA_M)
                ? aG + (size_t)row * K + ch * 8
                : bG + (size_t)(row - CTA_M) * K + ch * 8;
            cp_async16(dstS + (uint32_t)row * PITCH_B + (uint32_t)ch * 16, src);
        }
    };

    float acc[4][4][4];
    #pragma unroll
    for (int mt = 0; mt < 4; mt++)
        #pragma unroll
        for (int ni = 0; ni < 4; ni++)
            #pragma unroll
            for (int j = 0; j < 4; j++) acc[mt][ni][j] = 0.0f;

    load_stage(0, 0); cp_commit();
    load_stage(1, 1); cp_commit();
    load_stage(2, 2); cp_commit();

    for (int kt = 0; kt < num_kt; kt++) {
        cp_wait<STAGES - 2>();
        __syncthreads();

        if (kt + STAGES - 1 < num_kt) load_stage((kt + STAGES - 1) & (STAGES - 1), kt + STAGES - 1);
        cp_commit();

        const uint32_t soff = (uint32_t)(kt & (STAGES - 1)) * STAGE_BYTES;

        #pragma unroll
        for (int ks = 0; ks < 2; ks++) {
            const uint32_t ko = soff + (uint32_t)ks * 32;   // 16 halves = 32B
            uint32_t af[4][4];
            #pragma unroll
            for (int mt = 0; mt < 4; mt++)
                ldsm_x4(af[mt], aw_base + ko + (uint32_t)(mt * 16) * PITCH_B);
            uint32_t bf[4][2];
            #pragma unroll
            for (int np = 0; np < 2; np++) {
                uint32_t q[4];
                ldsm_x4(q, bw_base + ko + (uint32_t)(np * 16) * PITCH_B);
                bf[np * 2][0]     = q[0]; bf[np * 2][1]     = q[1];
                bf[np * 2 + 1][0] = q[2]; bf[np * 2 + 1][1] = q[3];
            }
            #pragma unroll
            for (int mt = 0; mt < 4; mt++)
                #pragma unroll
                for (int ni = 0; ni < 4; ni++)
                    mma_f16(acc[mt][ni], af[mt], bf[ni]);
        }
    }

    // -------- epilogue --------
    #pragma unroll
    for (int mt = 0; mt < 4; mt++) {
        const int row = m0 + wm * 64 + mt * 16 + g;
        #pragma unroll
        for (int ni = 0; ni < 4; ni++) {
            const int col = n0 + wn * 32 + ni * 8 + 2 * t4;
            const float2 bv = *reinterpret_cast<const float2*>(bias + col);
            float x0 = acc[mt][ni][0] + bv.x;
            float x1 = acc[mt][ni][1] + bv.y;
            float x2 = acc[mt][ni][2] + bv.x;
            float x3 = acc[mt][ni][3] + bv.y;
            if (DO_GELU) {
                __half* out = (__half*)outp;
                __half2 h01 = __floats2half2_rn(gelu_exact(x0), gelu_exact(x1));
                __half2 h23 = __floats2half2_rn(gelu_exact(x2), gelu_exact(x3));
                *reinterpret_cast<__half2*>(out + (size_t)row * N + col)       = h01;
                *reinterpret_cast<__half2*>(out + (size_t)(row + 8) * N + col) = h23;
            } else {
                float* out = (float*)outp;
                float2 v01 = {x0, x1}, v23 = {x2, x3};
                *reinterpret_cast<float2*>(out + (size_t)row * N + col)       = v01;
                *reinterpret_cast<float2*>(out + (size_t)(row + 8) * N + col) = v23;
            }
        }
    }
}

// ============================================================================
// Host
// ============================================================================
extern "C" void kernel_launch(void* const* d_in, const int* in_sizes, int n_in,
                              void* d_out, int out_size) {
    const float* x  = (const float*)d_in[0];
    const float* w1 = (const float*)d_in[1];
    const float* b1 = (const float*)d_in[2];
    const float* w2 = (const float*)d_in[3];
    const float* b2 = (const float*)d_in[4];
    float* out = (float*)d_out;

    __half *Xh, *W1t, *W2t, *H;
    cudaGetSymbolAddress((void**)&Xh,  g_Xh);
    cudaGetSymbolAddress((void**)&W1t, g_W1t);
    cudaGetSymbolAddress((void**)&W2t, g_W2t);
    cudaGetSymbolAddress((void**)&H,   g_H);

    cudaFuncSetAttribute((const void*)mlp_gemm_h<1>,
                         cudaFuncAttributeMaxDynamicSharedMemorySize, SMEM_BYTES);
    cudaFuncSetAttribute((const void*)mlp_gemm_h<0>,
                         cudaFuncAttributeMaxDynamicSharedMemorySize, SMEM_BYTES);

    // Prepass: X -> fp16; W1, W2 -> fp16 transposed to [N][K]
    f32_to_f16_kernel<<<1184, 256>>>(x, Xh, (M_TOTAL * N_EMBD) / 4);
    transpose_f16_kernel<<<dim3(N_STATE / 32, N_EMBD / 32), dim3(32, 8)>>>(w1, W1t, N_EMBD, N_STATE);
    transpose_f16_kernel<<<dim3(N_EMBD / 32, N_STATE / 32), dim3(32, 8)>>>(w2, W2t, N_STATE, N_EMBD);

    // GEMM1: H = fp16(GELU(X @ W1 + b1))    grid 32 x 64
    mlp_gemm_h<1><<<dim3(N_STATE / CTA_N, M_TOTAL / CTA_M), 256, SMEM_BYTES>>>(
        Xh, W1t, b1, H, N_EMBD, N_STATE);

    // GEMM2: out = H @ W2 + b2              grid 8 x 64
    mlp_gemm_h<0><<<dim3(N_EMBD / CTA_N, M_TOTAL / CTA_M), 256, SMEM_BYTES>>>(
        H, W2t, b2, out, N_STATE, N_EMBD);
}

// round 6
// speedup vs baseline: 2.2454x; 1.0714x over previous
#include <cuda_runtime.h>
#include <cuda_fp16.h>
#include <cstdint>
#include <math.h>

// ============================================================================
// Shapes
// ============================================================================
#define M_TOTAL 8192
#define N_EMBD  1024
#define N_STATE 4096

// CTA 128x128x64, 8 warps of 64x32, 2 CTAs/SM
#define CTA_M  128
#define CTA_N  128
#define CTA_K  64                   // halves per k-tile (4 k-steps of 16)
#define STAGES 3

#define PITCH_B   144               // bytes per smem row (64 halves = 128B + 16B pad)
#define ROWS_PER_STAGE (CTA_M + CTA_N)              // 256
#define STAGE_BYTES    (ROWS_PER_STAGE * PITCH_B)   // 36864
#define SMEM_BYTES     (STAGES * STAGE_BYTES)       // 110592 (x2 CTAs = 216 KB/SM)

// Scratch (static; no allocation allowed)
__device__ __half g_Xh [(size_t)M_TOTAL * N_EMBD];       // 16 MB
__device__ __half g_W1t[(size_t)N_STATE * N_EMBD];       //  8 MB  [N][K]
__device__ __half g_W2t[(size_t)N_EMBD * N_STATE];       //  8 MB  [N][K]
__device__ __half g_H  [(size_t)M_TOTAL * N_STATE];      // 64 MB

// ============================================================================
// PTX helpers
// ============================================================================
__device__ __forceinline__ uint32_t smem_u32(const void* p) {
    uint32_t a;
    asm("{ .reg .u64 t; cvta.to.shared.u64 t, %1; cvt.u32.u64 %0, t; }" : "=r"(a) : "l"(p));
    return a;
}
__device__ __forceinline__ void cp_async16(uint32_t dst, const void* src) {
    asm volatile("cp.async.cg.shared.global [%0], [%1], 16;" :: "r"(dst), "l"(src));
}
__device__ __forceinline__ void cp_commit() {
    asm volatile("cp.async.commit_group;" ::: "memory");
}
template <int N>
__device__ __forceinline__ void cp_wait() {
    asm volatile("cp.async.wait_group %0;" :: "n"(N) : "memory");
}
__device__ __forceinline__ void ldsm_x4(uint32_t* r, uint32_t addr) {
    asm volatile("ldmatrix.sync.aligned.m8n8.x4.shared.b16 {%0,%1,%2,%3}, [%4];"
        : "=r"(r[0]), "=r"(r[1]), "=r"(r[2]), "=r"(r[3]) : "r"(addr));
}
__device__ __forceinline__ void mma_f16(float* c, const uint32_t* a, const uint32_t* b) {
    asm volatile(
        "mma.sync.aligned.m16n8k16.row.col.f32.f16.f16.f32 "
        "{%0,%1,%2,%3}, {%4,%5,%6,%7}, {%8,%9}, {%0,%1,%2,%3};"
        : "+f"(c[0]), "+f"(c[1]), "+f"(c[2]), "+f"(c[3])
        : "r"(a[0]), "r"(a[1]), "r"(a[2]), "r"(a[3]), "r"(b[0]), "r"(b[1]));
}
__device__ __forceinline__ float gelu_exact(float x) {
    return 0.5f * x * (1.0f + erff(x * 0.70710678118654752f));
}

// ============================================================================
// Prepass: fp32 -> fp16 (RNE) copy + 32x32 transpose
// ============================================================================
__global__ void f32_to_f16_kernel(const float* __restrict__ in, __half* __restrict__ out, int n4) {
    int stride = gridDim.x * blockDim.x;
    for (int i = blockIdx.x * blockDim.x + threadIdx.x; i < n4; i += stride) {
        float4 v = reinterpret_cast<const float4*>(in)[i];
        __half2* o = reinterpret_cast<__half2*>(out) + 2 * i;
        o[0] = __floats2half2_rn(v.x, v.y);
        o[1] = __floats2half2_rn(v.z, v.w);
    }
}
__global__ void transpose_f16_kernel(const float* __restrict__ in, __half* __restrict__ out,
                                     int rows, int cols) {
    __shared__ float tile[32][33];
    int bx = blockIdx.x * 32, by = blockIdx.y * 32;
    int tx = threadIdx.x;
    for (int r = threadIdx.y; r < 32; r += 8)
        tile[r][tx] = in[(size_t)(by + r) * cols + bx + tx];
    __syncthreads();
    for (int r = threadIdx.y; r < 32; r += 8)
        out[(size_t)(bx + r) * rows + by + tx] = __float2half_rn(tile[tx][r]);
}

// ============================================================================
// GEMM: out[M,N] = op(A[M,K] @ Bt[N,K]^T + bias)
//   A fp16 [M][K]; Bt fp16 [N][K]. DO_GELU=1 -> fp16 out (H), else fp32 out.
//   SMEM stage: 256 rows x 144B (rows 0-127 = A, 128-255 = B). Row stride
//   144B = nine 16B groups => 8 consecutive rows hit 8 distinct 16B bank
//   groups (9 mod 8 = 1): LDSM phases are conflict-free.
// ============================================================================
template <int DO_GELU>
__global__ void __launch_bounds__(256, 2)
mlp_gemm_h(const __half* __restrict__ A, const __half* __restrict__ Bt,
           const float* __restrict__ bias, void* __restrict__ outp,
           int K, int N)
{
    extern __shared__ __half smem[];
    const uint32_t smem_base = smem_u32(smem);

    const int tid  = threadIdx.x;
    const int wid  = tid >> 5;
    const int lane = tid & 31;
    const int g    = lane >> 2;
    const int t4   = lane & 3;
    const int wm   = wid & 1;           // 2 warps in M (64 rows)
    const int wn   = wid >> 1;          // 4 warps in N (32 cols)

    const int m0 = blockIdx.y * CTA_M;
    const int n0 = blockIdx.x * CTA_N;
    const int num_kt = K / CTA_K;

    // ---- per-lane ldmatrix offsets (bytes) ----
    const int mi = lane >> 3;
    const int r8 = lane & 7;
    const uint32_t a_lane = (uint32_t)(((mi & 1) * 8 + r8) * PITCH_B + (mi >> 1) * 16);
    const uint32_t b_lane = (uint32_t)(((mi >> 1) * 8 + r8) * PITCH_B + (mi & 1) * 16);
    const uint32_t aw_base = smem_base + (uint32_t)(wm * 64) * PITCH_B + a_lane;
    const uint32_t bw_base = smem_base + (uint32_t)(CTA_M + wn * 32) * PITCH_B + b_lane;

    // ---- stage loader: 256 rows x 8 chunks(16B) = 2048 chunks, 8 per thread ----
    auto load_stage = [&](int s, int kt) {
        uint32_t dstS = smem_base + (uint32_t)s * STAGE_BYTES;
        const __half* aG = A  + (size_t)m0 * K + kt * CTA_K;
        const __half* bG = Bt + (size_t)n0 * K + kt * CTA_K;
        #pragma unroll
        for (int i = 0; i < 8; i++) {
            int c   = tid + i * 256;
            int row = c >> 3, ch = c & 7;
            const __half* src = (row < CTA_M)
                ? aG + (size_t)row * K + ch * 8
                : bG + (size_t)(row - CTA_M) * K + ch * 8;
            cp_async16(dstS + (uint32_t)row * PITCH_B + (uint32_t)ch * 16, src);
        }
    };

    float acc[4][4][4];
    #pragma unroll
    for (int mt = 0; mt < 4; mt++)
        #pragma unroll
        for (int ni = 0; ni < 4; ni++)
            #pragma unroll
            for (int j = 0; j < 4; j++) acc[mt][ni][j] = 0.0f;

    load_stage(0, 0); cp_commit();
    load_stage(1, 1); cp_commit();

    int s_cur = 0, s_next = 2;          // stage being consumed / stage to fill
    for (int kt = 0; kt < num_kt; kt++) {
        cp_wait<STAGES - 2>();
        __syncthreads();

        if (kt + STAGES - 1 < num_kt) load_stage(s_next, kt + STAGES - 1);
        cp_commit();
        if (++s_next == STAGES) s_next = 0;

        const uint32_t soff = (uint32_t)s_cur * STAGE_BYTES;
        if (++s_cur == STAGES) s_cur = 0;

        #pragma unroll
        for (int ks = 0; ks < 4; ks++) {                  // 4 k-steps of 16
            const uint32_t ko = soff + (uint32_t)ks * 32; // 16 halves = 32B
            uint32_t af[4][4];
            #pragma unroll
            for (int mt = 0; mt < 4; mt++)
                ldsm_x4(af[mt], aw_base + ko + (uint32_t)(mt * 16) * PITCH_B);
            uint32_t bf[4][2];
            #pragma unroll
            for (int np = 0; np < 2; np++) {
                uint32_t q[4];
                ldsm_x4(q, bw_base + ko + (uint32_t)(np * 16) * PITCH_B);
                bf[np * 2][0]     = q[0]; bf[np * 2][1]     = q[1];
                bf[np * 2 + 1][0] = q[2]; bf[np * 2 + 1][1] = q[3];
            }
            #pragma unroll
            for (int mt = 0; mt < 4; mt++)
                #pragma unroll
                for (int ni = 0; ni < 4; ni++)
                    mma_f16(acc[mt][ni], af[mt], bf[ni]);
        }
    }

    // -------- epilogue --------
    #pragma unroll
    for (int mt = 0; mt < 4; mt++) {
        const int row = m0 + wm * 64 + mt * 16 + g;
        #pragma unroll
        for (int ni = 0; ni < 4; ni++) {
            const int col = n0 + wn * 32 + ni * 8 + 2 * t4;
            const float2 bv = *reinterpret_cast<const float2*>(bias + col);
            float x0 = acc[mt][ni][0] + bv.x;
            float x1 = acc[mt][ni][1] + bv.y;
            float x2 = acc[mt][ni][2] + bv.x;
            float x3 = acc[mt][ni][3] + bv.y;
            if (DO_GELU) {
                __half* out = (__half*)outp;
                __half2 h01 = __floats2half2_rn(gelu_exact(x0), gelu_exact(x1));
                __half2 h23 = __floats2half2_rn(gelu_exact(x2), gelu_exact(x3));
                *reinterpret_cast<__half2*>(out + (size_t)row * N + col)       = h01;
                *reinterpret_cast<__half2*>(out + (size_t)(row + 8) * N + col) = h23;
            } else {
                float* out = (float*)outp;
                float2 v01 = {x0, x1}, v23 = {x2, x3};
                *reinterpret_cast<float2*>(out + (size_t)row * N + col)       = v01;
                *reinterpret_cast<float2*>(out + (size_t)(row + 8) * N + col) = v23;
            }
        }
    }
}

// ============================================================================
// Host
// ============================================================================
extern "C" void kernel_launch(void* const* d_in, const int* in_sizes, int n_in,
                              void* d_out, int out_size) {
    const float* x  = (const float*)d_in[0];
    const float* w1 = (const float*)d_in[1];
    const float* b1 = (const float*)d_in[2];
    const float* w2 = (const float*)d_in[3];
    const float* b2 = (const float*)d_in[4];
    float* out = (float*)d_out;

    __half *Xh, *W1t, *W2t, *H;
    cudaGetSymbolAddress((void**)&Xh,  g_Xh);
    cudaGetSymbolAddress((void**)&W1t, g_W1t);
    cudaGetSymbolAddress((void**)&W2t, g_W2t);
    cudaGetSymbolAddress((void**)&H,   g_H);

    cudaFuncSetAttribute((const void*)mlp_gemm_h<1>,
                         cudaFuncAttributeMaxDynamicSharedMemorySize, SMEM_BYTES);
    cudaFuncSetAttribute((const void*)mlp_gemm_h<0>,
                         cudaFuncAttributeMaxDynamicSharedMemorySize, SMEM_BYTES);

    // Prepass: X -> fp16; W1, W2 -> fp16 transposed to [N][K]
    f32_to_f16_kernel<<<1184, 256>>>(x, Xh, (M_TOTAL * N_EMBD) / 4);
    transpose_f16_kernel<<<dim3(N_STATE / 32, N_EMBD / 32), dim3(32, 8)>>>(w1, W1t, N_EMBD, N_STATE);
    transpose_f16_kernel<<<dim3(N_EMBD / 32, N_STATE / 32), dim3(32, 8)>>>(w2, W2t, N_STATE, N_EMBD);

    // GEMM1: H = fp16(GELU(X @ W1 + b1))    grid 32 x 64
    mlp_gemm_h<1><<<dim3(N_STATE / CTA_N, M_TOTAL / CTA_M), 256, SMEM_BYTES>>>(
        Xh, W1t, b1, H, N_EMBD, N_STATE);

    // GEMM2: out = H @ W2 + b2              grid 8 x 64
    mlp_gemm_h<0><<<dim3(N_EMBD / CTA_N, M_TOTAL / CTA_M), 256, SMEM_BYTES>>>(
        H, W2t, b2, out, N_STATE, N_EMBD);
}